// round 1
// baseline (speedup 1.0000x reference)
#include <cuda_runtime.h>
#include <cuda_bf16.h>

// StixelLoss fused kernel.
// inputs:  (B=256, C=2, H=192, W=256) f32
// targets: (1, B, C, H, W) f32 (same linear layout after squeeze)
// out:     scalar f32 = ALPHA*bce_mean + BETA*cuts + GAMMA*dense

#define HH 192
#define WW 256
#define NBC 512   // B*C blocks

__global__ void sx_zero_kernel(float* out) {
    if (threadIdx.x == 0) out[0] = 0.0f;
}

__global__ __launch_bounds__(256)
void stixel_kernel(const float* __restrict__ inp,
                   const float* __restrict__ tgt,
                   float* __restrict__ out) {
    const int bc = blockIdx.x;          // b*2 + c
    const int c  = bc & 1;
    const int w  = threadIdx.x;

    const float* ip = inp + (size_t)bc * (HH * WW) + w;
    const float* tp = tgt + (size_t)bc * (HH * WW) + w;

    float bce   = 0.0f;
    float dense = 0.0f;
    int   cuts  = 0;
    int   prev  = 0;

    if (c == 0) {
        // channel 0: BCE + cuts count (all H rows)
        #pragma unroll 4
        for (int h = 0; h < HH; ++h) {
            float p = ip[h * WW];
            float t = tp[h * WW];
            float lp  = fmaxf(__logf(p), -100.0f);
            float l1p = fmaxf(__logf(1.0f - p), -100.0f);
            bce += t * lp + (1.0f - t) * l1p;
            cuts += (p > 0.5f) ? 1 : 0;
        }
    } else {
        // channel 1: BCE (all H rows) + dense scan (rows 0..H-2)
        #pragma unroll 4
        for (int h = 0; h < HH; ++h) {
            float p = ip[h * WW];
            float t = tp[h * WW];
            float lp  = fmaxf(__logf(p), -100.0f);
            float l1p = fmaxf(__logf(1.0f - p), -100.0f);
            bce += t * lp + (1.0f - t) * l1p;
            if (h < HH - 1) {
                bool m = (p > 0.5f);
                if (m && (prev != 0)) {
                    float d = (float)(h - prev);
                    dense += __fdividef(1.0f, d * d * d);
                }
                if (m) prev = h;
            }
        }
    }

    // combine per-thread terms (ALPHA=1, BETA=0.001, GAMMA=0.1)
    const float INV_N = 1.0f / (float)((size_t)NBC * HH * WW);
    float val = -bce * INV_N + 0.001f * (float)cuts + 0.1f * dense;

    // block reduction: warp shuffle, then cross-warp via shared
    __shared__ float sred[8];
    #pragma unroll
    for (int off = 16; off > 0; off >>= 1)
        val += __shfl_down_sync(0xffffffffu, val, off);
    int lane = threadIdx.x & 31;
    int wid  = threadIdx.x >> 5;
    if (lane == 0) sred[wid] = val;
    __syncthreads();
    if (wid == 0) {
        val = (lane < 8) ? sred[lane] : 0.0f;
        #pragma unroll
        for (int off = 4; off > 0; off >>= 1)
            val += __shfl_down_sync(0xffffffffu, val, off);
        if (lane == 0) atomicAdd(out, val);
    }
}

extern "C" void kernel_launch(void* const* d_in, const int* in_sizes, int n_in,
                              void* d_out, int out_size) {
    const float* inp = (const float*)d_in[0];
    const float* tgt = (const float*)d_in[1];
    float* out = (float*)d_out;

    sx_zero_kernel<<<1, 32>>>(out);
    stixel_kernel<<<NBC, 256>>>(inp, tgt, out);
}